// round 14
// baseline (speedup 1.0000x reference)
#include <cuda_runtime.h>
#include <cuda_bf16.h>
#include <math.h>
#include <stdint.h>

// Problem constants (fixed by the reference)
#define BB 2
#define SS 2048
#define DD 512
#define VV 32000
#define HH 4
#define DH 128
#define WW 3
#define NN (BB*SS)   // 4096
#define NCH 16       // 512 / 32 tf32 per 128B row chunk

// Scratch (device globals; no allocation allowed)
__device__ float g_wx  [NN*DD];
__device__ float g_ssrc[NN*HH];
__device__ float g_sdst[NN*HH];
__device__ uint32_t g_t0 [(size_t)NN*DD];     // activations (tf32 bits)
__device__ uint32_t g_t1 [(size_t)NN*DD];     // attn output (tf32 bits)
__device__ uint32_t g_t2 [(size_t)NN*DD];     // layer hand-off (tf32 bits)
__device__ uint32_t g_Wt4[(size_t)4*DD*DD];   // all 4 GAT weights (tf32 bits)
__device__ uint32_t g_Bt [(size_t)VV*DD];     // LM head weight (tf32 bits)

// ---------------------------------------------------------------------------
// PTX helpers (sm_80-era: cp.async, ldmatrix, mma.sync — valid at compute_103.
// tcgen05 is NOT available at the harness's virtual PTX target.)
// ---------------------------------------------------------------------------
__device__ __forceinline__ uint32_t smem_u32(const void* p) {
    uint32_t a;
    asm("{ .reg .u64 t; cvta.to.shared.u64 t, %1; cvt.u32.u64 %0, t; }"
        : "=r"(a) : "l"(p));
    return a;
}
__device__ __forceinline__ void cp_async16(uint32_t dst, const void* src) {
    asm volatile("cp.async.cg.shared.global [%0], [%1], 16;\n" :: "r"(dst), "l"(src));
}
#define CP_COMMIT() asm volatile("cp.async.commit_group;\n" ::: "memory")
template<int Nw> __device__ __forceinline__ void cp_wait() {
    asm volatile("cp.async.wait_group %0;\n" :: "n"(Nw) : "memory");
}
__device__ __forceinline__ void ldmatrix_x4(uint32_t& r0, uint32_t& r1,
                                            uint32_t& r2, uint32_t& r3, uint32_t addr) {
    asm volatile("ldmatrix.sync.aligned.m8n8.x4.shared.b16 {%0,%1,%2,%3}, [%4];\n"
                 : "=r"(r0), "=r"(r1), "=r"(r2), "=r"(r3) : "r"(addr));
}
// tf32 mma: fragments loaded with the SAME ldmatrix addressing as bf16 — each
// 32-bit register's two adjacent b16 slots reinterpret as one tf32 at half k.
__device__ __forceinline__ void mma_tf32(float* c,
                                         uint32_t a0, uint32_t a1, uint32_t a2, uint32_t a3,
                                         uint32_t b0, uint32_t b1) {
    asm volatile(
        "mma.sync.aligned.m16n8k8.row.col.f32.tf32.tf32.f32 "
        "{%0,%1,%2,%3}, {%4,%5,%6,%7}, {%8,%9}, {%0,%1,%2,%3};\n"
        : "+f"(c[0]), "+f"(c[1]), "+f"(c[2]), "+f"(c[3])
        : "r"(a0), "r"(a1), "r"(a2), "r"(a3), "r"(b0), "r"(b1));
}
__device__ __forceinline__ uint32_t f2tf32(float x) {
    uint32_t r;
    asm("cvt.rna.tf32.f32 %0, %1;" : "=r"(r) : "f"(x));
    return r;
}

// ---------------------------------------------------------------------------
// fp32 -> tf32 bits (generic, vectorized)
// ---------------------------------------------------------------------------
__global__ void conv_tf32_k(const float* __restrict__ src, uint32_t* __restrict__ dst)
{
    size_t i = (size_t)blockIdx.x * blockDim.x + threadIdx.x;
    size_t base = i * 4;
    float4 v = *(const float4*)(src + base);
    uint4 o;
    o.x = f2tf32(v.x); o.y = f2tf32(v.y); o.z = f2tf32(v.z); o.w = f2tf32(v.w);
    *(uint4*)(dst + base) = o;
}

// All 4 GAT weights in one launch: dst blocks of DD*DD each
__global__ void conv_w4_k(const float* __restrict__ w0, const float* __restrict__ w1,
                          const float* __restrict__ w2, const float* __restrict__ w3,
                          uint32_t* __restrict__ dst)
{
    const int per = (DD*DD)/4;   // float4 groups per weight
    int i = blockIdx.x * blockDim.x + threadIdx.x;
    int which = i / per;
    int off   = i % per;
    const float* src = (which == 0) ? w0 : (which == 1) ? w1 : (which == 2) ? w2 : w3;
    float4 v = *(const float4*)(src + (size_t)off*4);
    uint4 o;
    o.x = f2tf32(v.x); o.y = f2tf32(v.y); o.z = f2tf32(v.z); o.w = f2tf32(v.w);
    *(uint4*)(dst + (size_t)which*DD*DD + (size_t)off*4) = o;
}

// ---------------------------------------------------------------------------
// Fused embedding gather + tf32 convert
// ---------------------------------------------------------------------------
__global__ void gather_tf32_k(const int* __restrict__ ids,
                              const float* __restrict__ emb,
                              uint32_t* __restrict__ t0)
{
    int idx = blockIdx.x * blockDim.x + threadIdx.x;   // over NN*(DD/4)
    int n  = idx / (DD/4);
    int c  = (idx % (DD/4)) * 4;
    float4 v = *(const float4*)(emb + (size_t)ids[n]*DD + c);
    uint4 o;
    o.x = f2tf32(v.x); o.y = f2tf32(v.y); o.z = f2tf32(v.z); o.w = f2tf32(v.w);
    *(uint4*)(t0 + (size_t)n*DD + c) = o;
}

// ---------------------------------------------------------------------------
// Windowed GAT aggregation, fused with tf32 convert
// ---------------------------------------------------------------------------
__global__ void attn_tf32_k(const float* __restrict__ wx,
                            const float* __restrict__ ssrc,
                            const float* __restrict__ sdst,
                            uint32_t* __restrict__ t1)
{
    int n    = blockIdx.x;
    int h    = threadIdx.x >> 5;
    int lane = threadIdx.x & 31;
    int i    = n % SS;

    float sd = sdst[(size_t)n*HH + h];

    float e[2*WW];
    int   jn[2*WW];
    int cnt = 0;
    #pragma unroll
    for (int off = -WW; off <= WW; off++) {
        if (off == 0) continue;
        int ji = i + off;
        if (ji < 0 || ji >= SS) continue;
        int j = n + off;
        float v = ssrc[(size_t)j*HH + h] + sd;
        v = v >= 0.f ? v : 0.2f * v;
        e[cnt] = v; jn[cnt] = j; cnt++;
    }
    float m = -1e30f;
    for (int c = 0; c < cnt; c++) m = fmaxf(m, e[c]);
    float den = 0.f;
    for (int c = 0; c < cnt; c++) { e[c] = expf(e[c] - m); den += e[c]; }
    float inv = 1.f / (den + 1e-16f);

    int d = lane * 4;
    float acc[4] = {0.f, 0.f, 0.f, 0.f};
    for (int c = 0; c < cnt; c++) {
        const float4 xv = *(const float4*)(wx + (size_t)jn[c]*DD + h*DH + d);
        float al = e[c] * inv;
        acc[0] = fmaf(al, xv.x, acc[0]);
        acc[1] = fmaf(al, xv.y, acc[1]);
        acc[2] = fmaf(al, xv.z, acc[2]);
        acc[3] = fmaf(al, xv.w, acc[3]);
    }
    uint4 o;
    o.x = f2tf32(acc[0]); o.y = f2tf32(acc[1]);
    o.z = f2tf32(acc[2]); o.w = f2tf32(acc[3]);
    *(uint4*)(t1 + (size_t)n*DD + h*DH + d) = o;
}

// ---------------------------------------------------------------------------
// Unified tf32 GEMM: C[M, Ncols] = At[M,512] @ Bt[Ncols,512]^T (+bias)(+epi)
// CTA 128xBN, 8 warps (2m x 4n), warp tile 64x(BN/4). BK=32 (128B rows),
// 3-stage cp.async.
// EMIT 0: raw fp32 -> Cf (stride DD) AND fused attention scores
// EMIT 1: bias+ELU -> tf32 Ct (stride DD)
// EMIT 2: bias -> fp32 Cf (stride VV)
// ---------------------------------------------------------------------------
template<int BN> struct TFCfg {
    static constexpr int STAGE = (128 + BN) * 128;
    static constexpr int OFF_B = 16384;            // A: 128 rows * 128B
    static constexpr int NJ    = BN / 32;          // n8 frags per warp
    static constexpr int NG    = BN / 64;          // ldmatrix groups per warp
    static constexpr int WN    = BN / 4;           // warp tile N
    static constexpr int GRAN  = (128 + BN) * 8;   // 16B granules per stage
};

template<int BN, int EMIT>
__global__ void __launch_bounds__(256, (BN == 128 ? 2 : 1))
tf32_mma_k(const uint32_t* __restrict__ At,
           const uint32_t* __restrict__ Bt,
           const float* __restrict__ bias,
           float* __restrict__ Cf,
           uint32_t* __restrict__ Ct,
           const float* __restrict__ avec,   // EMIT 0: a[H][2*DH]
           float* __restrict__ ssrc,
           float* __restrict__ sdst)
{
    using C = TFCfg<BN>;
    extern __shared__ char smem[];
    const uint32_t sb = smem_u32(smem);
    const int tid  = threadIdx.x;
    const int wid  = tid >> 5;
    const int lane = tid & 31;
    const int row0 = blockIdx.x * 128;
    const int col0 = blockIdx.y * BN;

    const int warp_m = wid & 1;
    const int warp_n = wid >> 1;

    float acc[4][C::NJ][4];
    #pragma unroll
    for (int i = 0; i < 4; i++)
        #pragma unroll
        for (int j = 0; j < C::NJ; j++)
            #pragma unroll
            for (int q = 0; q < 4; q++) acc[i][j][q] = 0.f;

    auto load_stage = [&](int kk, uint32_t stage_base) {
        #pragma unroll
        for (int it = 0; it < C::GRAN/256; it++) {
            int g = tid + it*256;
            bool isA = (g < 1024);
            int gg  = isA ? g : (g - 1024);
            int row = gg >> 3;
            int gran = gg & 7;
            const uint32_t* src = (isA
                ? At + (size_t)(row0 + row)*DD
                : Bt + (size_t)(col0 + row)*DD) + kk + gran*4;
            uint32_t dst = stage_base + (isA ? 0u : (uint32_t)C::OFF_B)
                         + (uint32_t)row*128u + (uint32_t)((gran ^ (row & 7)) << 4);
            cp_async16(dst, src);
        }
    };

    load_stage(0,  sb);            CP_COMMIT();
    load_stage(32, sb + C::STAGE); CP_COMMIT();

    const int a_row  = warp_m*64 + (lane & 15);
    const int a_gsel = lane >> 4;
    const int b_row  = warp_n*C::WN + ((lane >> 4) << 3) + (lane & 7);
    const int b_gsel = (lane >> 3) & 1;

    for (int c = 0; c < NCH; c++) {
        cp_wait<1>();
        __syncthreads();

        if (c + 2 < NCH)
            load_stage((c+2)*32, sb + ((c+2)%3)*C::STAGE);
        CP_COMMIT();

        const uint32_t sA = sb + (c%3)*C::STAGE;
        const uint32_t sB = sA + C::OFF_B;

        #pragma unroll
        for (int s = 0; s < 4; s++) {   // four k8 (tf32) steps per 32-chunk
            uint32_t a[4][4];
            #pragma unroll
            for (int mi = 0; mi < 4; mi++) {
                int r = a_row + mi*16;
                int g = 2*s + a_gsel;
                uint32_t addr = sA + (uint32_t)r*128u + (uint32_t)((g ^ (r & 7)) << 4);
                ldmatrix_x4(a[mi][0], a[mi][1], a[mi][2], a[mi][3], addr);
            }
            uint32_t b[C::NJ][2];
            #pragma unroll
            for (int ng = 0; ng < C::NG; ng++) {
                int r = b_row + ng*16;
                int g = 2*s + b_gsel;
                uint32_t addr = sB + (uint32_t)r*128u + (uint32_t)((g ^ (r & 7)) << 4);
                uint32_t r0, r1, r2, r3;
                ldmatrix_x4(r0, r1, r2, r3, addr);
                b[ng*2+0][0] = r0; b[ng*2+0][1] = r1;
                b[ng*2+1][0] = r2; b[ng*2+1][1] = r3;
            }
            #pragma unroll
            for (int mi = 0; mi < 4; mi++)
                #pragma unroll
                for (int nj = 0; nj < C::NJ; nj++)
                    mma_tf32(acc[mi][nj], a[mi][0], a[mi][1], a[mi][2], a[mi][3],
                             b[nj][0], b[nj][1]);
        }
    }

    const int trow = lane >> 2;
    const int tcol = (lane & 3) * 2;
    const size_t cstride = (EMIT == 2) ? (size_t)VV : (size_t)DD;

    if (EMIT == 0) {
        // ---- write wx + fused per-head attention scores ----
        const int h = blockIdx.y;   // BN==128: one head per column block
        const float* as = avec + (size_t)h*2*DH;
        const float* ad = as + DH;
        float psrc[4][2], pdst[4][2];
        #pragma unroll
        for (int mi = 0; mi < 4; mi++) {
            psrc[mi][0] = psrc[mi][1] = 0.f;
            pdst[mi][0] = pdst[mi][1] = 0.f;
        }
        #pragma unroll
        for (int mi = 0; mi < 4; mi++) {
            const int mbase = row0 + warp_m*64 + mi*16 + trow;
            #pragma unroll
            for (int nj = 0; nj < C::NJ; nj++) {
                const int jl  = warp_n*C::WN + nj*8 + tcol;   // local col 0..127
                const int col = col0 + jl;
                float v0 = acc[mi][nj][0], v1 = acc[mi][nj][1];
                float v2 = acc[mi][nj][2], v3 = acc[mi][nj][3];
                *(float2*)(Cf + (size_t)mbase*DD + col)     = make_float2(v0, v1);
                *(float2*)(Cf + (size_t)(mbase+8)*DD + col) = make_float2(v2, v3);
                const float s0 = __ldg(as + jl), s1 = __ldg(as + jl + 1);
                const float d0 = __ldg(ad + jl), d1 = __ldg(ad + jl + 1);
                psrc[mi][0] = fmaf(v0, s0, fmaf(v1, s1, psrc[mi][0]));
                psrc[mi][1] = fmaf(v2, s0, fmaf(v3, s1, psrc[mi][1]));
                pdst[mi][0] = fmaf(v0, d0, fmaf(v1, d1, pdst[mi][0]));
                pdst[mi][1] = fmaf(v2, d0, fmaf(v3, d1, pdst[mi][1]));
            }
        }
        #pragma unroll
        for (int off = 1; off <= 2; off <<= 1)
            #pragma unroll
            for (int mi = 0; mi < 4; mi++)
                #pragma unroll
                for (int p = 0; p < 2; p++) {
                    psrc[mi][p] += __shfl_xor_sync(0xffffffffu, psrc[mi][p], off);
                    pdst[mi][p] += __shfl_xor_sync(0xffffffffu, pdst[mi][p], off);
                }
        __syncthreads();                 // all warps done reading stage smem
        float* red = (float*)smem;       // [2][4 warp_n][128 row] = 4KB
        if ((lane & 3) == 0) {
            #pragma unroll
            for (int mi = 0; mi < 4; mi++)
                #pragma unroll
                for (int p = 0; p < 2; p++) {
                    int rl = warp_m*64 + mi*16 + trow + p*8;
                    red[0*512 + warp_n*128 + rl] = psrc[mi][p];
                    red[1*512 + warp_n*128 + rl] = pdst[mi][p];
                }
        }
        __syncthreads();
        {
            int sd = tid >> 7;           // 0: src, 1: dst
            int rl = tid & 127;
            float s = red[sd*512 + 0*128 + rl] + red[sd*512 + 1*128 + rl]
                    + red[sd*512 + 2*128 + rl] + red[sd*512 + 3*128 + rl];
            float* outp = sd ? sdst : ssrc;
            outp[(size_t)(row0 + rl)*HH + h] = s;
        }
        return;
    }

    #pragma unroll
    for (int mi = 0; mi < 4; mi++) {
        const int mbase = row0 + warp_m*64 + mi*16 + trow;
        #pragma unroll
        for (int nj = 0; nj < C::NJ; nj++) {
            const int col = col0 + warp_n*C::WN + nj*8 + tcol;
            float v0 = acc[mi][nj][0], v1 = acc[mi][nj][1];
            float v2 = acc[mi][nj][2], v3 = acc[mi][nj][3];
            const float b0 = __ldg(bias + col);
            const float b1 = __ldg(bias + col + 1);
            v0 += b0; v1 += b1; v2 += b0; v3 += b1;
            if (EMIT == 1) {
                v0 = v0 > 0.f ? v0 : (expf(v0) - 1.f);
                v1 = v1 > 0.f ? v1 : (expf(v1) - 1.f);
                v2 = v2 > 0.f ? v2 : (expf(v2) - 1.f);
                v3 = v3 > 0.f ? v3 : (expf(v3) - 1.f);
                *(uint2*)(Ct + (size_t)mbase*cstride + col) =
                    make_uint2(f2tf32(v0), f2tf32(v1));
                *(uint2*)(Ct + (size_t)(mbase+8)*cstride + col) =
                    make_uint2(f2tf32(v2), f2tf32(v3));
            } else {  // EMIT == 2
                *(float2*)(Cf + (size_t)mbase*cstride + col)     = make_float2(v0, v1);
                *(float2*)(Cf + (size_t)(mbase+8)*cstride + col) = make_float2(v2, v3);
            }
        }
    }
}

// ---------------------------------------------------------------------------
// Host side
// ---------------------------------------------------------------------------
extern "C" void kernel_launch(void* const* d_in, const int* in_sizes, int n_in,
                              void* d_out, int out_size)
{
    const int*   ids = (const int*)  d_in[0];
    const float* emb = (const float*)d_in[1];
    const float* W1  = (const float*)d_in[2];
    const float* a1  = (const float*)d_in[3];
    const float* o1w = (const float*)d_in[4];
    const float* o1b = (const float*)d_in[5];
    const float* W2  = (const float*)d_in[6];
    const float* a2  = (const float*)d_in[7];
    const float* o2w = (const float*)d_in[8];
    const float* o2b = (const float*)d_in[9];
    const float* lmw = (const float*)d_in[10];
    const float* lmb = (const float*)d_in[11];
    float* out = (float*)d_out;

    float *pwx, *pssrc, *psdst;
    uint32_t *pt0, *pt1, *pt2, *pWt4, *pBt;
    cudaGetSymbolAddress((void**)&pwx,   g_wx);
    cudaGetSymbolAddress((void**)&pssrc, g_ssrc);
    cudaGetSymbolAddress((void**)&psdst, g_sdst);
    cudaGetSymbolAddress((void**)&pt0,   g_t0);
    cudaGetSymbolAddress((void**)&pt1,   g_t1);
    cudaGetSymbolAddress((void**)&pt2,   g_t2);
    cudaGetSymbolAddress((void**)&pWt4,  g_Wt4);
    cudaGetSymbolAddress((void**)&pBt,   g_Bt);

    // One-time init (runs on the eager correctness call, before graph capture):
    // attributes + side stream / events for fork-join overlap of weight converts.
    static cudaStream_t s2 = nullptr;
    static cudaEvent_t ev_fork = nullptr, ev_w4 = nullptr, ev_lmw = nullptr;
    static bool init_done = false;
    if (!init_done) {
        cudaFuncSetAttribute((const void*)tf32_mma_k<128,0>,
            cudaFuncAttributeMaxDynamicSharedMemorySize, 3*TFCfg<128>::STAGE);
        cudaFuncSetAttribute((const void*)tf32_mma_k<128,1>,
            cudaFuncAttributeMaxDynamicSharedMemorySize, 3*TFCfg<128>::STAGE);
        cudaFuncSetAttribute((const void*)tf32_mma_k<256,2>,
            cudaFuncAttributeMaxDynamicSharedMemorySize, 3*TFCfg<256>::STAGE);
        cudaStreamCreateWithFlags(&s2, cudaStreamNonBlocking);
        cudaEventCreateWithFlags(&ev_fork, cudaEventDisableTiming);
        cudaEventCreateWithFlags(&ev_w4,   cudaEventDisableTiming);
        cudaEventCreateWithFlags(&ev_lmw,  cudaEventDisableTiming);
        init_done = true;
    }

    const int GS = 3*TFCfg<128>::STAGE;   // 96 KB
    const int LS = 3*TFCfg<256>::STAGE;   // 144 KB
    const dim3 gg(NN/128, DD/128);

    uint32_t* pW1 = pWt4;
    uint32_t* pO1 = pWt4 + (size_t)1*DD*DD;
    uint32_t* pW2 = pWt4 + (size_t)2*DD*DD;
    uint32_t* pO2 = pWt4 + (size_t)3*DD*DD;

    // ---- Fork: weight converts on side stream, gather on main stream ----
    cudaEventRecord(ev_fork, 0);
    cudaStreamWaitEvent(s2, ev_fork, 0);
    conv_w4_k<<<(4*(DD*DD/4))/256, 256, 0, s2>>>(W1, o1w, W2, o2w, pWt4);
    cudaEventRecord(ev_w4, s2);
    conv_tf32_k<<<(VV*(DD/4))/256, 256, 0, s2>>>(lmw, pBt);   // overlaps GAT layers
    cudaEventRecord(ev_lmw, s2);

    gather_tf32_k<<<(NN*(DD/4))/256, 256>>>(ids, emb, pt0);
    cudaStreamWaitEvent(0, ev_w4, 0);     // GAT weights ready

    // ---- Layer 1 ----
    tf32_mma_k<128,0><<<gg, 256, GS>>>(pt0, pW1, nullptr, pwx, nullptr, a1, pssrc, psdst);
    attn_tf32_k<<<NN, 128>>>(pwx, pssrc, psdst, pt1);
    tf32_mma_k<128,1><<<gg, 256, GS>>>(pt1, pO1, o1b, nullptr, pt2, nullptr, nullptr, nullptr);

    // ---- Layer 2 ----
    tf32_mma_k<128,0><<<gg, 256, GS>>>(pt2, pW2, nullptr, pwx, nullptr, a2, pssrc, psdst);
    attn_tf32_k<<<NN, 128>>>(pwx, pssrc, psdst, pt1);
    tf32_mma_k<128,1><<<gg, 256, GS>>>(pt1, pO2, o2b, nullptr, pt0, nullptr, nullptr, nullptr);

    // ---- Join, then LM head (grid.x = M fast-varying -> B-tile L2 reuse) ----
    cudaStreamWaitEvent(0, ev_lmw, 0);    // lmhead weights ready
    dim3 g(NN/128, VV/256);
    tf32_mma_k<256,2><<<g, 256, LS>>>(pt0, pBt, lmb, out, nullptr, nullptr, nullptr, nullptr);
}

// round 15
// speedup vs baseline: 1.0070x; 1.0070x over previous
#include <cuda_runtime.h>
#include <cuda_bf16.h>
#include <math.h>
#include <stdint.h>

// Problem constants (fixed by the reference)
#define BB 2
#define SS 2048
#define DD 512
#define VV 32000
#define HH 4
#define DH 128
#define WW 3
#define NN (BB*SS)   // 4096
#define NCH 16       // 512 / 32 tf32 per 128B row chunk

// Scratch (device globals; no allocation allowed)
__device__ float g_wx  [NN*DD];
__device__ float g_ssrc[NN*HH];
__device__ float g_sdst[NN*HH];
__device__ uint32_t g_t0 [(size_t)NN*DD];     // activations (tf32 bits)
__device__ uint32_t g_t1 [(size_t)NN*DD];     // attn output (tf32 bits)
__device__ uint32_t g_t2 [(size_t)NN*DD];     // layer hand-off (tf32 bits)
__device__ uint32_t g_Wt4[(size_t)4*DD*DD];   // all 4 GAT weights (tf32 bits)
__device__ uint32_t g_Bt [(size_t)VV*DD];     // LM head weight (tf32 bits)

// ---------------------------------------------------------------------------
// PTX helpers (sm_80-era: cp.async, ldmatrix, mma.sync — valid at compute_103.
// tcgen05 is NOT available at the harness's virtual PTX target.)
// ---------------------------------------------------------------------------
__device__ __forceinline__ uint32_t smem_u32(const void* p) {
    uint32_t a;
    asm("{ .reg .u64 t; cvta.to.shared.u64 t, %1; cvt.u32.u64 %0, t; }"
        : "=r"(a) : "l"(p));
    return a;
}
__device__ __forceinline__ void cp_async16(uint32_t dst, const void* src) {
    asm volatile("cp.async.cg.shared.global [%0], [%1], 16;\n" :: "r"(dst), "l"(src));
}
#define CP_COMMIT() asm volatile("cp.async.commit_group;\n" ::: "memory")
template<int Nw> __device__ __forceinline__ void cp_wait() {
    asm volatile("cp.async.wait_group %0;\n" :: "n"(Nw) : "memory");
}
__device__ __forceinline__ void ldmatrix_x4(uint32_t& r0, uint32_t& r1,
                                            uint32_t& r2, uint32_t& r3, uint32_t addr) {
    asm volatile("ldmatrix.sync.aligned.m8n8.x4.shared.b16 {%0,%1,%2,%3}, [%4];\n"
                 : "=r"(r0), "=r"(r1), "=r"(r2), "=r"(r3) : "r"(addr));
}
// tf32 mma: fragments loaded with the SAME ldmatrix addressing as bf16 — each
// 32-bit register's two adjacent b16 slots reinterpret as one tf32 at half k.
__device__ __forceinline__ void mma_tf32(float* c,
                                         uint32_t a0, uint32_t a1, uint32_t a2, uint32_t a3,
                                         uint32_t b0, uint32_t b1) {
    asm volatile(
        "mma.sync.aligned.m16n8k8.row.col.f32.tf32.tf32.f32 "
        "{%0,%1,%2,%3}, {%4,%5,%6,%7}, {%8,%9}, {%0,%1,%2,%3};\n"
        : "+f"(c[0]), "+f"(c[1]), "+f"(c[2]), "+f"(c[3])
        : "r"(a0), "r"(a1), "r"(a2), "r"(a3), "r"(b0), "r"(b1));
}
__device__ __forceinline__ uint32_t f2tf32(float x) {
    uint32_t r;
    asm("cvt.rna.tf32.f32 %0, %1;" : "=r"(r) : "f"(x));
    return r;
}

// ---------------------------------------------------------------------------
// fp32 -> tf32 bits (generic, vectorized)
// ---------------------------------------------------------------------------
__global__ void conv_tf32_k(const float* __restrict__ src, uint32_t* __restrict__ dst)
{
    size_t i = (size_t)blockIdx.x * blockDim.x + threadIdx.x;
    size_t base = i * 4;
    float4 v = *(const float4*)(src + base);
    uint4 o;
    o.x = f2tf32(v.x); o.y = f2tf32(v.y); o.z = f2tf32(v.z); o.w = f2tf32(v.w);
    *(uint4*)(dst + base) = o;
}

// All 4 GAT weights in one launch: dst blocks of DD*DD each
__global__ void conv_w4_k(const float* __restrict__ w0, const float* __restrict__ w1,
                          const float* __restrict__ w2, const float* __restrict__ w3,
                          uint32_t* __restrict__ dst)
{
    const int per = (DD*DD)/4;   // float4 groups per weight
    int i = blockIdx.x * blockDim.x + threadIdx.x;
    int which = i / per;
    int off   = i % per;
    const float* src = (which == 0) ? w0 : (which == 1) ? w1 : (which == 2) ? w2 : w3;
    float4 v = *(const float4*)(src + (size_t)off*4);
    uint4 o;
    o.x = f2tf32(v.x); o.y = f2tf32(v.y); o.z = f2tf32(v.z); o.w = f2tf32(v.w);
    *(uint4*)(dst + (size_t)which*DD*DD + (size_t)off*4) = o;
}

// ---------------------------------------------------------------------------
// Fused embedding gather + tf32 convert
// ---------------------------------------------------------------------------
__global__ void gather_tf32_k(const int* __restrict__ ids,
                              const float* __restrict__ emb,
                              uint32_t* __restrict__ t0)
{
    int idx = blockIdx.x * blockDim.x + threadIdx.x;   // over NN*(DD/4)
    int n  = idx / (DD/4);
    int c  = (idx % (DD/4)) * 4;
    float4 v = *(const float4*)(emb + (size_t)ids[n]*DD + c);
    uint4 o;
    o.x = f2tf32(v.x); o.y = f2tf32(v.y); o.z = f2tf32(v.z); o.w = f2tf32(v.w);
    *(uint4*)(t0 + (size_t)n*DD + c) = o;
}

// ---------------------------------------------------------------------------
// Windowed GAT aggregation, fused with tf32 convert.
// Fixed 6-iteration unrolled neighbor loop: out-of-range neighbors get a
// clamped (safe) address and score -1e30 -> exp underflows to exactly 0,
// so results are bitwise identical to the variable-trip version.
// ---------------------------------------------------------------------------
__global__ void attn_tf32_k(const float* __restrict__ wx,
                            const float* __restrict__ ssrc,
                            const float* __restrict__ sdst,
                            uint32_t* __restrict__ t1)
{
    int n    = blockIdx.x;
    int h    = threadIdx.x >> 5;
    int lane = threadIdx.x & 31;
    int i    = n % SS;

    const float sd = sdst[(size_t)n*HH + h];
    const int offs[6] = {-3, -2, -1, 1, 2, 3};

    int   jn[6];
    float e[6];
    #pragma unroll
    for (int c = 0; c < 6; c++) {
        int off = offs[c];
        int ji  = i + off;
        bool ok = (ji >= 0) && (ji < SS);
        jn[c] = ok ? (n + off) : n;          // clamped safe address
        float v = ok ? (ssrc[(size_t)jn[c]*HH + h] + sd) : -1e30f;
        e[c] = v >= 0.f ? v : 0.2f * v;      // LeakyReLU (no-op on -1e30)
    }
    float m = e[0];
    #pragma unroll
    for (int c = 1; c < 6; c++) m = fmaxf(m, e[c]);
    float den = 0.f;
    #pragma unroll
    for (int c = 0; c < 6; c++) { e[c] = expf(e[c] - m); den += e[c]; }
    float inv = 1.f / (den + 1e-16f);

    int d = lane * 4;
    // batch all 6 neighbor loads (MLP 6)
    float4 xv[6];
    #pragma unroll
    for (int c = 0; c < 6; c++)
        xv[c] = *(const float4*)(wx + (size_t)jn[c]*DD + h*DH + d);

    float acc[4] = {0.f, 0.f, 0.f, 0.f};
    #pragma unroll
    for (int c = 0; c < 6; c++) {
        float al = e[c] * inv;
        acc[0] = fmaf(al, xv[c].x, acc[0]);
        acc[1] = fmaf(al, xv[c].y, acc[1]);
        acc[2] = fmaf(al, xv[c].z, acc[2]);
        acc[3] = fmaf(al, xv[c].w, acc[3]);
    }
    uint4 o;
    o.x = f2tf32(acc[0]); o.y = f2tf32(acc[1]);
    o.z = f2tf32(acc[2]); o.w = f2tf32(acc[3]);
    *(uint4*)(t1 + (size_t)n*DD + h*DH + d) = o;
}

// ---------------------------------------------------------------------------
// Unified tf32 GEMM: C[M, Ncols] = At[M,512] @ Bt[Ncols,512]^T (+bias)(+epi)
// CTA 128xBN, 8 warps (2m x 4n), warp tile 64x(BN/4). BK=32 (128B rows),
// 3-stage cp.async.
// EMIT 0: raw fp32 -> Cf (stride DD) AND fused attention scores (BN=128)
// EMIT 1: bias+ELU -> tf32 Ct (stride DD)
// EMIT 2: bias -> fp32 Cf (stride VV)
// ---------------------------------------------------------------------------
template<int BN> struct TFCfg {
    static constexpr int STAGE = (128 + BN) * 128;
    static constexpr int OFF_B = 16384;            // A: 128 rows * 128B
    static constexpr int NJ    = BN / 32;          // n8 frags per warp
    static constexpr int NG    = BN / 64;          // ldmatrix groups per warp
    static constexpr int WN    = BN / 4;           // warp tile N
    static constexpr int GRAN  = (128 + BN) * 8;   // 16B granules per stage
};

template<int BN, int EMIT>
__global__ void __launch_bounds__(256, (BN >= 256 ? 1 : 2))
tf32_mma_k(const uint32_t* __restrict__ At,
           const uint32_t* __restrict__ Bt,
           const float* __restrict__ bias,
           float* __restrict__ Cf,
           uint32_t* __restrict__ Ct,
           const float* __restrict__ avec,   // EMIT 0: a[H][2*DH]
           float* __restrict__ ssrc,
           float* __restrict__ sdst)
{
    using C = TFCfg<BN>;
    extern __shared__ char smem[];
    const uint32_t sb = smem_u32(smem);
    const int tid  = threadIdx.x;
    const int wid  = tid >> 5;
    const int lane = tid & 31;
    const int row0 = blockIdx.x * 128;
    const int col0 = blockIdx.y * BN;

    const int warp_m = wid & 1;
    const int warp_n = wid >> 1;

    float acc[4][C::NJ][4];
    #pragma unroll
    for (int i = 0; i < 4; i++)
        #pragma unroll
        for (int j = 0; j < C::NJ; j++)
            #pragma unroll
            for (int q = 0; q < 4; q++) acc[i][j][q] = 0.f;

    auto load_stage = [&](int kk, uint32_t stage_base) {
        #pragma unroll
        for (int it = 0; it < C::GRAN/256; it++) {
            int g = tid + it*256;
            bool isA = (g < 1024);
            int gg  = isA ? g : (g - 1024);
            int row = gg >> 3;
            int gran = gg & 7;
            const uint32_t* src = (isA
                ? At + (size_t)(row0 + row)*DD
                : Bt + (size_t)(col0 + row)*DD) + kk + gran*4;
            uint32_t dst = stage_base + (isA ? 0u : (uint32_t)C::OFF_B)
                         + (uint32_t)row*128u + (uint32_t)((gran ^ (row & 7)) << 4);
            cp_async16(dst, src);
        }
    };

    load_stage(0,  sb);            CP_COMMIT();
    load_stage(32, sb + C::STAGE); CP_COMMIT();

    const int a_row  = warp_m*64 + (lane & 15);
    const int a_gsel = lane >> 4;
    const int b_row  = warp_n*C::WN + ((lane >> 4) << 3) + (lane & 7);
    const int b_gsel = (lane >> 3) & 1;

    for (int c = 0; c < NCH; c++) {
        cp_wait<1>();
        __syncthreads();

        if (c + 2 < NCH)
            load_stage((c+2)*32, sb + ((c+2)%3)*C::STAGE);
        CP_COMMIT();

        const uint32_t sA = sb + (c%3)*C::STAGE;
        const uint32_t sB = sA + C::OFF_B;

        #pragma unroll
        for (int s = 0; s < 4; s++) {   // four k8 (tf32) steps per 32-chunk
            uint32_t a[4][4];
            #pragma unroll
            for (int mi = 0; mi < 4; mi++) {
                int r = a_row + mi*16;
                int g = 2*s + a_gsel;
                uint32_t addr = sA + (uint32_t)r*128u + (uint32_t)((g ^ (r & 7)) << 4);
                ldmatrix_x4(a[mi][0], a[mi][1], a[mi][2], a[mi][3], addr);
            }
            uint32_t b[C::NJ][2];
            #pragma unroll
            for (int ng = 0; ng < C::NG; ng++) {
                int r = b_row + ng*16;
                int g = 2*s + b_gsel;
                uint32_t addr = sB + (uint32_t)r*128u + (uint32_t)((g ^ (r & 7)) << 4);
                uint32_t r0, r1, r2, r3;
                ldmatrix_x4(r0, r1, r2, r3, addr);
                b[ng*2+0][0] = r0; b[ng*2+0][1] = r1;
                b[ng*2+1][0] = r2; b[ng*2+1][1] = r3;
            }
            #pragma unroll
            for (int mi = 0; mi < 4; mi++)
                #pragma unroll
                for (int nj = 0; nj < C::NJ; nj++)
                    mma_tf32(acc[mi][nj], a[mi][0], a[mi][1], a[mi][2], a[mi][3],
                             b[nj][0], b[nj][1]);
        }
    }

    const int trow = lane >> 2;
    const int tcol = (lane & 3) * 2;
    const size_t cstride = (EMIT == 2) ? (size_t)VV : (size_t)DD;

    if (EMIT == 0) {
        // ---- write wx + fused per-head attention scores ----
        const int h = blockIdx.y;   // BN==128: one head per column block
        const float* as = avec + (size_t)h*2*DH;
        const float* ad = as + DH;
        float psrc[4][2], pdst[4][2];
        #pragma unroll
        for (int mi = 0; mi < 4; mi++) {
            psrc[mi][0] = psrc[mi][1] = 0.f;
            pdst[mi][0] = pdst[mi][1] = 0.f;
        }
        #pragma unroll
        for (int mi = 0; mi < 4; mi++) {
            const int mbase = row0 + warp_m*64 + mi*16 + trow;
            #pragma unroll
            for (int nj = 0; nj < C::NJ; nj++) {
                const int jl  = warp_n*C::WN + nj*8 + tcol;   // local col 0..127
                const int col = col0 + jl;
                float v0 = acc[mi][nj][0], v1 = acc[mi][nj][1];
                float v2 = acc[mi][nj][2], v3 = acc[mi][nj][3];
                *(float2*)(Cf + (size_t)mbase*DD + col)     = make_float2(v0, v1);
                *(float2*)(Cf + (size_t)(mbase+8)*DD + col) = make_float2(v2, v3);
                const float s0 = __ldg(as + jl), s1 = __ldg(as + jl + 1);
                const float d0 = __ldg(ad + jl), d1 = __ldg(ad + jl + 1);
                psrc[mi][0] = fmaf(v0, s0, fmaf(v1, s1, psrc[mi][0]));
                psrc[mi][1] = fmaf(v2, s0, fmaf(v3, s1, psrc[mi][1]));
                pdst[mi][0] = fmaf(v0, d0, fmaf(v1, d1, pdst[mi][0]));
                pdst[mi][1] = fmaf(v2, d0, fmaf(v3, d1, pdst[mi][1]));
            }
        }
        #pragma unroll
        for (int off = 1; off <= 2; off <<= 1)
            #pragma unroll
            for (int mi = 0; mi < 4; mi++)
                #pragma unroll
                for (int p = 0; p < 2; p++) {
                    psrc[mi][p] += __shfl_xor_sync(0xffffffffu, psrc[mi][p], off);
                    pdst[mi][p] += __shfl_xor_sync(0xffffffffu, pdst[mi][p], off);
                }
        __syncthreads();                 // all warps done reading stage smem
        float* red = (float*)smem;       // [2][4 warp_n][128 row] = 4KB
        if ((lane & 3) == 0) {
            #pragma unroll
            for (int mi = 0; mi < 4; mi++)
                #pragma unroll
                for (int p = 0; p < 2; p++) {
                    int rl = warp_m*64 + mi*16 + trow + p*8;
                    red[0*512 + warp_n*128 + rl] = psrc[mi][p];
                    red[1*512 + warp_n*128 + rl] = pdst[mi][p];
                }
        }
        __syncthreads();
        {
            int sd = tid >> 7;           // 0: src, 1: dst
            int rl = tid & 127;
            float s = red[sd*512 + 0*128 + rl] + red[sd*512 + 1*128 + rl]
                    + red[sd*512 + 2*128 + rl] + red[sd*512 + 3*128 + rl];
            float* outp = sd ? sdst : ssrc;
            outp[(size_t)(row0 + rl)*HH + h] = s;
        }
        return;
    }

    #pragma unroll
    for (int mi = 0; mi < 4; mi++) {
        const int mbase = row0 + warp_m*64 + mi*16 + trow;
        #pragma unroll
        for (int nj = 0; nj < C::NJ; nj++) {
            const int col = col0 + warp_n*C::WN + nj*8 + tcol;
            float v0 = acc[mi][nj][0], v1 = acc[mi][nj][1];
            float v2 = acc[mi][nj][2], v3 = acc[mi][nj][3];
            const float b0 = __ldg(bias + col);
            const float b1 = __ldg(bias + col + 1);
            v0 += b0; v1 += b1; v2 += b0; v3 += b1;
            if (EMIT == 1) {
                v0 = v0 > 0.f ? v0 : (expf(v0) - 1.f);
                v1 = v1 > 0.f ? v1 : (expf(v1) - 1.f);
                v2 = v2 > 0.f ? v2 : (expf(v2) - 1.f);
                v3 = v3 > 0.f ? v3 : (expf(v3) - 1.f);
                *(uint2*)(Ct + (size_t)mbase*cstride + col) =
                    make_uint2(f2tf32(v0), f2tf32(v1));
                *(uint2*)(Ct + (size_t)(mbase+8)*cstride + col) =
                    make_uint2(f2tf32(v2), f2tf32(v3));
            } else {  // EMIT == 2
                *(float2*)(Cf + (size_t)mbase*cstride + col)     = make_float2(v0, v1);
                *(float2*)(Cf + (size_t)(mbase+8)*cstride + col) = make_float2(v2, v3);
            }
        }
    }
}

// ---------------------------------------------------------------------------
// Host side
// ---------------------------------------------------------------------------
extern "C" void kernel_launch(void* const* d_in, const int* in_sizes, int n_in,
                              void* d_out, int out_size)
{
    const int*   ids = (const int*)  d_in[0];
    const float* emb = (const float*)d_in[1];
    const float* W1  = (const float*)d_in[2];
    const float* a1  = (const float*)d_in[3];
    const float* o1w = (const float*)d_in[4];
    const float* o1b = (const float*)d_in[5];
    const float* W2  = (const float*)d_in[6];
    const float* a2  = (const float*)d_in[7];
    const float* o2w = (const float*)d_in[8];
    const float* o2b = (const float*)d_in[9];
    const float* lmw = (const float*)d_in[10];
    const float* lmb = (const float*)d_in[11];
    float* out = (float*)d_out;

    float *pwx, *pssrc, *psdst;
    uint32_t *pt0, *pt1, *pt2, *pWt4, *pBt;
    cudaGetSymbolAddress((void**)&pwx,   g_wx);
    cudaGetSymbolAddress((void**)&pssrc, g_ssrc);
    cudaGetSymbolAddress((void**)&psdst, g_sdst);
    cudaGetSymbolAddress((void**)&pt0,   g_t0);
    cudaGetSymbolAddress((void**)&pt1,   g_t1);
    cudaGetSymbolAddress((void**)&pt2,   g_t2);
    cudaGetSymbolAddress((void**)&pWt4,  g_Wt4);
    cudaGetSymbolAddress((void**)&pBt,   g_Bt);

    // One-time init (runs on the eager correctness call, before graph capture)
    static cudaStream_t s2 = nullptr;
    static cudaEvent_t ev_fork = nullptr, ev_w4 = nullptr, ev_lmw = nullptr;
    static bool init_done = false;
    if (!init_done) {
        cudaFuncSetAttribute((const void*)tf32_mma_k<128,0>,
            cudaFuncAttributeMaxDynamicSharedMemorySize, 3*TFCfg<128>::STAGE);
        cudaFuncSetAttribute((const void*)tf32_mma_k<64,1>,
            cudaFuncAttributeMaxDynamicSharedMemorySize, 3*TFCfg<64>::STAGE);
        cudaFuncSetAttribute((const void*)tf32_mma_k<256,2>,
            cudaFuncAttributeMaxDynamicSharedMemorySize, 3*TFCfg<256>::STAGE);
        cudaStreamCreateWithFlags(&s2, cudaStreamNonBlocking);
        cudaEventCreateWithFlags(&ev_fork, cudaEventDisableTiming);
        cudaEventCreateWithFlags(&ev_w4,   cudaEventDisableTiming);
        cudaEventCreateWithFlags(&ev_lmw,  cudaEventDisableTiming);
        init_done = true;
    }

    const int GS1 = 3*TFCfg<128>::STAGE;  // 96 KB  (GEMM1, fused scores)
    const int GS2 = 3*TFCfg<64>::STAGE;   // 72 KB  (GEMM2, BN=64, 256 CTAs)
    const int LS  = 3*TFCfg<256>::STAGE;  // 144 KB (lmhead)
    const dim3 gg1(NN/128, DD/128);       // (32, 4)
    const dim3 gg2(NN/128, DD/64);        // (32, 8)

    uint32_t* pW1 = pWt4;
    uint32_t* pO1 = pWt4 + (size_t)1*DD*DD;
    uint32_t* pW2 = pWt4 + (size_t)2*DD*DD;
    uint32_t* pO2 = pWt4 + (size_t)3*DD*DD;

    // ---- Fork: weight converts on side stream, gather on main stream ----
    cudaEventRecord(ev_fork, 0);
    cudaStreamWaitEvent(s2, ev_fork, 0);
    conv_w4_k<<<(4*(DD*DD/4))/256, 256, 0, s2>>>(W1, o1w, W2, o2w, pWt4);
    cudaEventRecord(ev_w4, s2);
    conv_tf32_k<<<(VV*(DD/4))/256, 256, 0, s2>>>(lmw, pBt);   // overlaps GAT layers
    cudaEventRecord(ev_lmw, s2);

    gather_tf32_k<<<(NN*(DD/4))/256, 256>>>(ids, emb, pt0);
    cudaStreamWaitEvent(0, ev_w4, 0);     // GAT weights ready

    // ---- Layer 1 ----
    tf32_mma_k<128,0><<<gg1, 256, GS1>>>(pt0, pW1, nullptr, pwx, nullptr, a1, pssrc, psdst);
    attn_tf32_k<<<NN, 128>>>(pwx, pssrc, psdst, pt1);
    tf32_mma_k<64,1><<<gg2, 256, GS2>>>(pt1, pO1, o1b, nullptr, pt2, nullptr, nullptr, nullptr);

    // ---- Layer 2 ----
    tf32_mma_k<128,0><<<gg1, 256, GS1>>>(pt2, pW2, nullptr, pwx, nullptr, a2, pssrc, psdst);
    attn_tf32_k<<<NN, 128>>>(pwx, pssrc, psdst, pt1);
    tf32_mma_k<64,1><<<gg2, 256, GS2>>>(pt1, pO2, o2b, nullptr, pt0, nullptr, nullptr, nullptr);

    // ---- Join, then LM head (grid.x = M fast-varying -> B-tile L2 reuse) ----
    cudaStreamWaitEvent(0, ev_lmw, 0);    // lmhead weights ready
    dim3 g(NN/128, VV/256);
    tf32_mma_k<256,2><<<g, 256, LS>>>(pt0, pBt, lmb, out, nullptr, nullptr, nullptr, nullptr);
}

// round 16
// speedup vs baseline: 1.0082x; 1.0012x over previous
#include <cuda_runtime.h>
#include <cuda_bf16.h>
#include <math.h>
#include <stdint.h>

// Problem constants (fixed by the reference)
#define BB 2
#define SS 2048
#define DD 512
#define VV 32000
#define HH 4
#define DH 128
#define WW 3
#define NN (BB*SS)   // 4096
#define NCH 16       // 512 / 32 tf32 per 128B row chunk

// Scratch (device globals; no allocation allowed)
__device__ float g_wx  [NN*DD];
__device__ float g_ssrc[NN*HH];
__device__ float g_sdst[NN*HH];
__device__ uint32_t g_t0 [(size_t)NN*DD];     // activations (tf32 bits)
__device__ uint32_t g_t1 [(size_t)NN*DD];     // attn output (tf32 bits)
__device__ uint32_t g_t2 [(size_t)NN*DD];     // layer hand-off (tf32 bits)
__device__ uint32_t g_Wt4[(size_t)4*DD*DD];   // all 4 GAT weights (tf32 bits)
__device__ uint32_t g_Bt [(size_t)VV*DD];     // LM head weight (tf32 bits)

// ---------------------------------------------------------------------------
// PTX helpers (sm_80-era: cp.async, ldmatrix, mma.sync — valid at compute_103.
// tcgen05 is NOT available at the harness's virtual PTX target.)
// ---------------------------------------------------------------------------
__device__ __forceinline__ uint32_t smem_u32(const void* p) {
    uint32_t a;
    asm("{ .reg .u64 t; cvta.to.shared.u64 t, %1; cvt.u32.u64 %0, t; }"
        : "=r"(a) : "l"(p));
    return a;
}
__device__ __forceinline__ void cp_async16(uint32_t dst, const void* src) {
    asm volatile("cp.async.cg.shared.global [%0], [%1], 16;\n" :: "r"(dst), "l"(src));
}
#define CP_COMMIT() asm volatile("cp.async.commit_group;\n" ::: "memory")
template<int Nw> __device__ __forceinline__ void cp_wait() {
    asm volatile("cp.async.wait_group %0;\n" :: "n"(Nw) : "memory");
}
__device__ __forceinline__ void ldmatrix_x4(uint32_t& r0, uint32_t& r1,
                                            uint32_t& r2, uint32_t& r3, uint32_t addr) {
    asm volatile("ldmatrix.sync.aligned.m8n8.x4.shared.b16 {%0,%1,%2,%3}, [%4];\n"
                 : "=r"(r0), "=r"(r1), "=r"(r2), "=r"(r3) : "r"(addr));
}
// tf32 mma: fragments loaded with the SAME ldmatrix addressing as bf16 — each
// 32-bit register's two adjacent b16 slots reinterpret as one tf32 at half k.
__device__ __forceinline__ void mma_tf32(float* c,
                                         uint32_t a0, uint32_t a1, uint32_t a2, uint32_t a3,
                                         uint32_t b0, uint32_t b1) {
    asm volatile(
        "mma.sync.aligned.m16n8k8.row.col.f32.tf32.tf32.f32 "
        "{%0,%1,%2,%3}, {%4,%5,%6,%7}, {%8,%9}, {%0,%1,%2,%3};\n"
        : "+f"(c[0]), "+f"(c[1]), "+f"(c[2]), "+f"(c[3])
        : "r"(a0), "r"(a1), "r"(a2), "r"(a3), "r"(b0), "r"(b1));
}
__device__ __forceinline__ uint32_t f2tf32(float x) {
    uint32_t r;
    asm("cvt.rna.tf32.f32 %0, %1;" : "=r"(r) : "f"(x));
    return r;
}

// ---------------------------------------------------------------------------
// fp32 -> tf32 bits (generic, vectorized)
// ---------------------------------------------------------------------------
__global__ void conv_tf32_k(const float* __restrict__ src, uint32_t* __restrict__ dst)
{
    size_t i = (size_t)blockIdx.x * blockDim.x + threadIdx.x;
    size_t base = i * 4;
    float4 v = *(const float4*)(src + base);
    uint4 o;
    o.x = f2tf32(v.x); o.y = f2tf32(v.y); o.z = f2tf32(v.z); o.w = f2tf32(v.w);
    *(uint4*)(dst + base) = o;
}

// All 4 GAT weights in one launch: dst blocks of DD*DD each
__global__ void conv_w4_k(const float* __restrict__ w0, const float* __restrict__ w1,
                          const float* __restrict__ w2, const float* __restrict__ w3,
                          uint32_t* __restrict__ dst)
{
    const int per = (DD*DD)/4;   // float4 groups per weight
    int i = blockIdx.x * blockDim.x + threadIdx.x;
    int which = i / per;
    int off   = i % per;
    const float* src = (which == 0) ? w0 : (which == 1) ? w1 : (which == 2) ? w2 : w3;
    float4 v = *(const float4*)(src + (size_t)off*4);
    uint4 o;
    o.x = f2tf32(v.x); o.y = f2tf32(v.y); o.z = f2tf32(v.z); o.w = f2tf32(v.w);
    *(uint4*)(dst + (size_t)which*DD*DD + (size_t)off*4) = o;
}

// ---------------------------------------------------------------------------
// Fused embedding gather + tf32 convert
// ---------------------------------------------------------------------------
__global__ void gather_tf32_k(const int* __restrict__ ids,
                              const float* __restrict__ emb,
                              uint32_t* __restrict__ t0)
{
    int idx = blockIdx.x * blockDim.x + threadIdx.x;   // over NN*(DD/4)
    int n  = idx / (DD/4);
    int c  = (idx % (DD/4)) * 4;
    float4 v = *(const float4*)(emb + (size_t)ids[n]*DD + c);
    uint4 o;
    o.x = f2tf32(v.x); o.y = f2tf32(v.y); o.z = f2tf32(v.z); o.w = f2tf32(v.w);
    *(uint4*)(t0 + (size_t)n*DD + c) = o;
}

// ---------------------------------------------------------------------------
// Windowed GAT aggregation, fused with tf32 convert.
// Fixed 6-iteration unrolled neighbor loop (bitwise identical to masked form).
// ---------------------------------------------------------------------------
__global__ void attn_tf32_k(const float* __restrict__ wx,
                            const float* __restrict__ ssrc,
                            const float* __restrict__ sdst,
                            uint32_t* __restrict__ t1)
{
    int n    = blockIdx.x;
    int h    = threadIdx.x >> 5;
    int lane = threadIdx.x & 31;
    int i    = n % SS;

    const float sd = sdst[(size_t)n*HH + h];
    const int offs[6] = {-3, -2, -1, 1, 2, 3};

    int   jn[6];
    float e[6];
    #pragma unroll
    for (int c = 0; c < 6; c++) {
        int off = offs[c];
        int ji  = i + off;
        bool ok = (ji >= 0) && (ji < SS);
        jn[c] = ok ? (n + off) : n;          // clamped safe address
        float v = ok ? (ssrc[(size_t)jn[c]*HH + h] + sd) : -1e30f;
        e[c] = v >= 0.f ? v : 0.2f * v;      // LeakyReLU (no-op on -1e30)
    }
    float m = e[0];
    #pragma unroll
    for (int c = 1; c < 6; c++) m = fmaxf(m, e[c]);
    float den = 0.f;
    #pragma unroll
    for (int c = 0; c < 6; c++) { e[c] = expf(e[c] - m); den += e[c]; }
    float inv = 1.f / (den + 1e-16f);

    int d = lane * 4;
    float4 xv[6];
    #pragma unroll
    for (int c = 0; c < 6; c++)
        xv[c] = *(const float4*)(wx + (size_t)jn[c]*DD + h*DH + d);

    float acc[4] = {0.f, 0.f, 0.f, 0.f};
    #pragma unroll
    for (int c = 0; c < 6; c++) {
        float al = e[c] * inv;
        acc[0] = fmaf(al, xv[c].x, acc[0]);
        acc[1] = fmaf(al, xv[c].y, acc[1]);
        acc[2] = fmaf(al, xv[c].z, acc[2]);
        acc[3] = fmaf(al, xv[c].w, acc[3]);
    }
    uint4 o;
    o.x = f2tf32(acc[0]); o.y = f2tf32(acc[1]);
    o.z = f2tf32(acc[2]); o.w = f2tf32(acc[3]);
    *(uint4*)(t1 + (size_t)n*DD + h*DH + d) = o;
}

// ---------------------------------------------------------------------------
// Unified tf32 GEMM: C[M, Ncols] = At[M,512] @ Bt[Ncols,512]^T (+bias)(+epi)
// CTA BMxBN, 8 warps (2m x 4n), warp tile (BM/2)x(BN/4). BK=32 (128B rows),
// 3-stage cp.async.
// EMIT 0: raw fp32 -> Cf (stride DD) AND fused attention scores (BN=128)
// EMIT 1: bias+ELU -> tf32 Ct (stride DD)
// EMIT 2: bias -> fp32 Cf (stride VV)
// ---------------------------------------------------------------------------
template<int BM, int BN> struct TFCfg {
    static constexpr int STAGE = (BM + BN) * 128;
    static constexpr int OFF_B = BM * 128;         // A: BM rows * 128B
    static constexpr int MI    = BM / 32;          // m16 frags per warp
    static constexpr int NJ    = BN / 32;          // n8 frags per warp
    static constexpr int NG    = BN / 64;          // ldmatrix groups per warp
    static constexpr int WM    = BM / 2;           // warp tile M
    static constexpr int WN    = BN / 4;           // warp tile N
    static constexpr int GRAN  = (BM + BN) * 8;    // 16B granules per stage
};

template<int BM, int BN, int EMIT>
__global__ void __launch_bounds__(256, (BN >= 256 ? 1 : 2))
tf32_mma_k(const uint32_t* __restrict__ At,
           const uint32_t* __restrict__ Bt,
           const float* __restrict__ bias,
           float* __restrict__ Cf,
           uint32_t* __restrict__ Ct,
           const float* __restrict__ avec,   // EMIT 0: a[H][2*DH]
           float* __restrict__ ssrc,
           float* __restrict__ sdst)
{
    using C = TFCfg<BM, BN>;
    extern __shared__ char smem[];
    const uint32_t sb = smem_u32(smem);
    const int tid  = threadIdx.x;
    const int wid  = tid >> 5;
    const int lane = tid & 31;
    const int row0 = blockIdx.x * BM;
    const int col0 = blockIdx.y * BN;

    const int warp_m = wid & 1;
    const int warp_n = wid >> 1;

    float acc[C::MI][C::NJ][4];
    #pragma unroll
    for (int i = 0; i < C::MI; i++)
        #pragma unroll
        for (int j = 0; j < C::NJ; j++)
            #pragma unroll
            for (int q = 0; q < 4; q++) acc[i][j][q] = 0.f;

    auto load_stage = [&](int kk, uint32_t stage_base) {
        #pragma unroll
        for (int it = 0; it < C::GRAN/256; it++) {
            int g = tid + it*256;
            bool isA = (g < BM*8);
            int gg  = isA ? g : (g - BM*8);
            int row = gg >> 3;
            int gran = gg & 7;
            const uint32_t* src = (isA
                ? At + (size_t)(row0 + row)*DD
                : Bt + (size_t)(col0 + row)*DD) + kk + gran*4;
            uint32_t dst = stage_base + (isA ? 0u : (uint32_t)C::OFF_B)
                         + (uint32_t)row*128u + (uint32_t)((gran ^ (row & 7)) << 4);
            cp_async16(dst, src);
        }
    };

    load_stage(0,  sb);            CP_COMMIT();
    load_stage(32, sb + C::STAGE); CP_COMMIT();

    const int a_row  = warp_m*C::WM + (lane & 15);
    const int a_gsel = lane >> 4;
    const int b_row  = warp_n*C::WN + ((lane >> 4) << 3) + (lane & 7);
    const int b_gsel = (lane >> 3) & 1;

    for (int c = 0; c < NCH; c++) {
        cp_wait<1>();
        __syncthreads();

        if (c + 2 < NCH)
            load_stage((c+2)*32, sb + ((c+2)%3)*C::STAGE);
        CP_COMMIT();

        const uint32_t sA = sb + (c%3)*C::STAGE;
        const uint32_t sB = sA + C::OFF_B;

        #pragma unroll
        for (int s = 0; s < 4; s++) {   // four k8 (tf32) steps per 32-chunk
            uint32_t a[C::MI][4];
            #pragma unroll
            for (int mi = 0; mi < C::MI; mi++) {
                int r = a_row + mi*16;
                int g = 2*s + a_gsel;
                uint32_t addr = sA + (uint32_t)r*128u + (uint32_t)((g ^ (r & 7)) << 4);
                ldmatrix_x4(a[mi][0], a[mi][1], a[mi][2], a[mi][3], addr);
            }
            uint32_t b[C::NJ][2];
            #pragma unroll
            for (int ng = 0; ng < C::NG; ng++) {
                int r = b_row + ng*16;
                int g = 2*s + b_gsel;
                uint32_t addr = sB + (uint32_t)r*128u + (uint32_t)((g ^ (r & 7)) << 4);
                uint32_t r0, r1, r2, r3;
                ldmatrix_x4(r0, r1, r2, r3, addr);
                b[ng*2+0][0] = r0; b[ng*2+0][1] = r1;
                b[ng*2+1][0] = r2; b[ng*2+1][1] = r3;
            }
            #pragma unroll
            for (int mi = 0; mi < C::MI; mi++)
                #pragma unroll
                for (int nj = 0; nj < C::NJ; nj++)
                    mma_tf32(acc[mi][nj], a[mi][0], a[mi][1], a[mi][2], a[mi][3],
                             b[nj][0], b[nj][1]);
        }
    }

    const int trow = lane >> 2;
    const int tcol = (lane & 3) * 2;
    const size_t cstride = (EMIT == 2) ? (size_t)VV : (size_t)DD;

    if (EMIT == 0) {
        // ---- write wx + fused per-head attention scores ----
        const int h = blockIdx.y;   // BN==128: one head per column block
        const float* as = avec + (size_t)h*2*DH;
        const float* ad = as + DH;
        float psrc[C::MI][2], pdst[C::MI][2];
        #pragma unroll
        for (int mi = 0; mi < C::MI; mi++) {
            psrc[mi][0] = psrc[mi][1] = 0.f;
            pdst[mi][0] = pdst[mi][1] = 0.f;
        }
        #pragma unroll
        for (int mi = 0; mi < C::MI; mi++) {
            const int mbase = row0 + warp_m*C::WM + mi*16 + trow;
            #pragma unroll
            for (int nj = 0; nj < C::NJ; nj++) {
                const int jl  = warp_n*C::WN + nj*8 + tcol;   // local col 0..127
                const int col = col0 + jl;
                float v0 = acc[mi][nj][0], v1 = acc[mi][nj][1];
                float v2 = acc[mi][nj][2], v3 = acc[mi][nj][3];
                *(float2*)(Cf + (size_t)mbase*DD + col)     = make_float2(v0, v1);
                *(float2*)(Cf + (size_t)(mbase+8)*DD + col) = make_float2(v2, v3);
                const float s0 = __ldg(as + jl), s1 = __ldg(as + jl + 1);
                const float d0 = __ldg(ad + jl), d1 = __ldg(ad + jl + 1);
                psrc[mi][0] = fmaf(v0, s0, fmaf(v1, s1, psrc[mi][0]));
                psrc[mi][1] = fmaf(v2, s0, fmaf(v3, s1, psrc[mi][1]));
                pdst[mi][0] = fmaf(v0, d0, fmaf(v1, d1, pdst[mi][0]));
                pdst[mi][1] = fmaf(v2, d0, fmaf(v3, d1, pdst[mi][1]));
            }
        }
        #pragma unroll
        for (int off = 1; off <= 2; off <<= 1)
            #pragma unroll
            for (int mi = 0; mi < C::MI; mi++)
                #pragma unroll
                for (int p = 0; p < 2; p++) {
                    psrc[mi][p] += __shfl_xor_sync(0xffffffffu, psrc[mi][p], off);
                    pdst[mi][p] += __shfl_xor_sync(0xffffffffu, pdst[mi][p], off);
                }
        __syncthreads();                 // all warps done reading stage smem
        float* red = (float*)smem;       // [2][4 warp_n][BM rows]
        if ((lane & 3) == 0) {
            #pragma unroll
            for (int mi = 0; mi < C::MI; mi++)
                #pragma unroll
                for (int p = 0; p < 2; p++) {
                    int rl = warp_m*C::WM + mi*16 + trow + p*8;
                    red[0*4*BM + warp_n*BM + rl] = psrc[mi][p];
                    red[1*4*BM + warp_n*BM + rl] = pdst[mi][p];
                }
        }
        __syncthreads();
        if (tid < 2*BM) {
            int sd = tid / BM;           // 0: src, 1: dst
            int rl = tid % BM;
            float s = red[sd*4*BM + 0*BM + rl] + red[sd*4*BM + 1*BM + rl]
                    + red[sd*4*BM + 2*BM + rl] + red[sd*4*BM + 3*BM + rl];
            float* outp = sd ? sdst : ssrc;
            outp[(size_t)(row0 + rl)*HH + h] = s;
        }
        return;
    }

    #pragma unroll
    for (int mi = 0; mi < C::MI; mi++) {
        const int mbase = row0 + warp_m*C::WM + mi*16 + trow;
        #pragma unroll
        for (int nj = 0; nj < C::NJ; nj++) {
            const int col = col0 + warp_n*C::WN + nj*8 + tcol;
            float v0 = acc[mi][nj][0], v1 = acc[mi][nj][1];
            float v2 = acc[mi][nj][2], v3 = acc[mi][nj][3];
            const float b0 = __ldg(bias + col);
            const float b1 = __ldg(bias + col + 1);
            v0 += b0; v1 += b1; v2 += b0; v3 += b1;
            if (EMIT == 1) {
                v0 = v0 > 0.f ? v0 : (expf(v0) - 1.f);
                v1 = v1 > 0.f ? v1 : (expf(v1) - 1.f);
                v2 = v2 > 0.f ? v2 : (expf(v2) - 1.f);
                v3 = v3 > 0.f ? v3 : (expf(v3) - 1.f);
                *(uint2*)(Ct + (size_t)mbase*cstride + col) =
                    make_uint2(f2tf32(v0), f2tf32(v1));
                *(uint2*)(Ct + (size_t)(mbase+8)*cstride + col) =
                    make_uint2(f2tf32(v2), f2tf32(v3));
            } else {  // EMIT == 2
                *(float2*)(Cf + (size_t)mbase*cstride + col)     = make_float2(v0, v1);
                *(float2*)(Cf + (size_t)(mbase+8)*cstride + col) = make_float2(v2, v3);
            }
        }
    }
}

// ---------------------------------------------------------------------------
// Host side
// ---------------------------------------------------------------------------
extern "C" void kernel_launch(void* const* d_in, const int* in_sizes, int n_in,
                              void* d_out, int out_size)
{
    const int*   ids = (const int*)  d_in[0];
    const float* emb = (const float*)d_in[1];
    const float* W1  = (const float*)d_in[2];
    const float* a1  = (const float*)d_in[3];
    const float* o1w = (const float*)d_in[4];
    const float* o1b = (const float*)d_in[5];
    const float* W2  = (const float*)d_in[6];
    const float* a2  = (const float*)d_in[7];
    const float* o2w = (const float*)d_in[8];
    const float* o2b = (const float*)d_in[9];
    const float* lmw = (const float*)d_in[10];
    const float* lmb = (const float*)d_in[11];
    float* out = (float*)d_out;

    float *pwx, *pssrc, *psdst;
    uint32_t *pt0, *pt1, *pt2, *pWt4, *pBt;
    cudaGetSymbolAddress((void**)&pwx,   g_wx);
    cudaGetSymbolAddress((void**)&pssrc, g_ssrc);
    cudaGetSymbolAddress((void**)&psdst, g_sdst);
    cudaGetSymbolAddress((void**)&pt0,   g_t0);
    cudaGetSymbolAddress((void**)&pt1,   g_t1);
    cudaGetSymbolAddress((void**)&pt2,   g_t2);
    cudaGetSymbolAddress((void**)&pWt4,  g_Wt4);
    cudaGetSymbolAddress((void**)&pBt,   g_Bt);

    // One-time init (runs on the eager correctness call, before graph capture)
    static cudaStream_t s2 = nullptr;
    static cudaEvent_t ev_fork = nullptr, ev_w4 = nullptr, ev_lmw = nullptr;
    static bool init_done = false;
    if (!init_done) {
        cudaFuncSetAttribute((const void*)tf32_mma_k<64,128,0>,
            cudaFuncAttributeMaxDynamicSharedMemorySize, 3*TFCfg<64,128>::STAGE);
        cudaFuncSetAttribute((const void*)tf32_mma_k<128,64,1>,
            cudaFuncAttributeMaxDynamicSharedMemorySize, 3*TFCfg<128,64>::STAGE);
        cudaFuncSetAttribute((const void*)tf32_mma_k<128,256,2>,
            cudaFuncAttributeMaxDynamicSharedMemorySize, 3*TFCfg<128,256>::STAGE);
        cudaStreamCreateWithFlags(&s2, cudaStreamNonBlocking);
        cudaEventCreateWithFlags(&ev_fork, cudaEventDisableTiming);
        cudaEventCreateWithFlags(&ev_w4,   cudaEventDisableTiming);
        cudaEventCreateWithFlags(&ev_lmw,  cudaEventDisableTiming);
        init_done = true;
    }

    const int GS1 = 3*TFCfg<64,128>::STAGE;   // 72 KB (GEMM1, fused scores)
    const int GS2 = 3*TFCfg<128,64>::STAGE;   // 72 KB (GEMM2)
    const int LS  = 3*TFCfg<128,256>::STAGE;  // 144 KB (lmhead)
    const dim3 gg1(NN/64, DD/128);            // (64, 4) = 256 CTAs
    const dim3 gg2(NN/128, DD/64);            // (32, 8) = 256 CTAs

    uint32_t* pW1 = pWt4;
    uint32_t* pO1 = pWt4 + (size_t)1*DD*DD;
    uint32_t* pW2 = pWt4 + (size_t)2*DD*DD;
    uint32_t* pO2 = pWt4 + (size_t)3*DD*DD;

    // ---- Fork: weight converts on side stream, gather on main stream ----
    cudaEventRecord(ev_fork, 0);
    cudaStreamWaitEvent(s2, ev_fork, 0);
    conv_w4_k<<<(4*(DD*DD/4))/256, 256, 0, s2>>>(W1, o1w, W2, o2w, pWt4);
    cudaEventRecord(ev_w4, s2);
    conv_tf32_k<<<(VV*(DD/4))/256, 256, 0, s2>>>(lmw, pBt);   // overlaps GAT layers
    cudaEventRecord(ev_lmw, s2);

    gather_tf32_k<<<(NN*(DD/4))/256, 256>>>(ids, emb, pt0);
    cudaStreamWaitEvent(0, ev_w4, 0);     // GAT weights ready

    // ---- Layer 1 ----
    tf32_mma_k<64,128,0><<<gg1, 256, GS1>>>(pt0, pW1, nullptr, pwx, nullptr, a1, pssrc, psdst);
    attn_tf32_k<<<NN, 128>>>(pwx, pssrc, psdst, pt1);
    tf32_mma_k<128,64,1><<<gg2, 256, GS2>>>(pt1, pO1, o1b, nullptr, pt2, nullptr, nullptr, nullptr);

    // ---- Layer 2 ----
    tf32_mma_k<64,128,0><<<gg1, 256, GS1>>>(pt2, pW2, nullptr, pwx, nullptr, a2, pssrc, psdst);
    attn_tf32_k<<<NN, 128>>>(pwx, pssrc, psdst, pt1);
    tf32_mma_k<128,64,1><<<gg2, 256, GS2>>>(pt1, pO2, o2b, nullptr, pt0, nullptr, nullptr, nullptr);

    // ---- Join, then LM head (grid.x = M fast-varying -> B-tile L2 reuse) ----
    cudaStreamWaitEvent(0, ev_lmw, 0);    // lmhead weights ready
    dim3 g(NN/128, VV/256);
    tf32_mma_k<128,256,2><<<g, 256, LS>>>(pt0, pBt, lmb, out, nullptr, nullptr, nullptr, nullptr);
}